// round 11
// baseline (speedup 1.0000x reference)
#include <cuda_runtime.h>
#include <cstdint>

constexpr int Bc=4, Nn=2048, Dd=256, Hh=4;
constexpr int TJ=32, NT=Nn/TJ;

__device__ float g_Wh  [Bc*Nn*Dd];
__device__ float g_WhR [Bc*Nn*Dd];
__device__ float g_esrc[Bc*Hh*Nn];
__device__ float g_edst[Bc*Hh*Nn];
__device__ float g_p0  [Bc*Nn*Dd];
__device__ float g_p1  [Bc*Nn*Dd];
__device__ float g_alpha_s[Bc*Hh*Nn*Nn];

__device__ __forceinline__ float totf(float x){
    uint32_t u; asm("cvt.rna.tf32.f32 %0, %1;" : "=r"(u) : "f"(x));
    return __uint_as_float(u);
}
__device__ __forceinline__ void mma8(float* d, float4 a, float2 b){
    asm volatile("mma.sync.aligned.m16n8k8.row.col.f32.tf32.tf32.f32 "
        "{%0,%1,%2,%3}, {%4,%5,%6,%7}, {%8,%9}, {%0,%1,%2,%3};"
        : "+f"(d[0]), "+f"(d[1]), "+f"(d[2]), "+f"(d[3])
        : "r"(__float_as_uint(a.x)), "r"(__float_as_uint(a.y)),
          "r"(__float_as_uint(a.z)), "r"(__float_as_uint(a.w)),
          "r"(__float_as_uint(b.x)), "r"(__float_as_uint(b.y)));
}
__device__ __forceinline__ void cpasync16(void* smem_p, const void* gmem){
    unsigned s = (unsigned)__cvta_generic_to_shared(smem_p);
    asm volatile("cp.async.cg.shared.global [%0], [%1], 16;" :: "r"(s), "l"(gmem));
}
#define CP_COMMIT() asm volatile("cp.async.commit_group;")
__device__ __forceinline__ void cp_wait_tail(int rem){
    if(rem>=2)      asm volatile("cp.async.wait_group 2;");
    else if(rem==1) asm volatile("cp.async.wait_group 1;");
    else            asm volatile("cp.async.wait_group 0;");
}

constexpr int AST=36, BST=72;
constexpr int ABUF=128*AST, BBUF=32*BST;
constexpr int STG = ABUF + BBUF;                 // 6912 floats
constexpr int SMEM_PIPE4 = 4*STG*4;              // 110592 B (k1)
constexpr int SMEM_PIPE2 = 2*STG*4;              // 55296 B (gat_gemm)

// ---------------------------------------------------------------------------
// K1: Wh = h @ W via 3-term tf32 split HMMA (fp32-accurate result).
// ---------------------------------------------------------------------------
__global__ __launch_bounds__(256,2)
void gemm_h_w(const float* __restrict__ A, const float* __restrict__ Bw){
    extern __shared__ float sm[];
    const int tid = threadIdx.x, lane = tid & 31;
    const int i0 = blockIdx.x * 128;
    const int n0 = blockIdx.y * 64;
    const int NT_K = 8;
    const int mq = (tid>>5)&3, nq = tid>>7;

    float acc[2][4][4];
#pragma unroll
    for(int mf=0;mf<2;mf++)
#pragma unroll
        for(int nf=0;nf<4;nf++)
#pragma unroll
            for(int q=0;q<4;q++) acc[mf][nf][q]=0.f;

    const int a_row = tid>>3, a_ch = tid&7;
    const int b_j   = tid>>4, b_ch = tid&15;

    auto stage = [&](int t){
        const int j0 = t*TJ;
        float* Asm = sm + (t&3)*STG;
        float* Bsm = Asm + ABUF;
#pragma unroll
        for(int k=0;k<4;k++){
            int row = a_row + k*32;
            cpasync16(Asm + row*AST + a_ch*4,
                      A + (size_t)(i0+row)*256 + j0 + a_ch*4);
        }
#pragma unroll
        for(int k=0;k<2;k++){
            int j = b_j + k*16;
            cpasync16(Bsm + j*BST + b_ch*4,
                      Bw + (size_t)(j0+j)*256 + n0 + b_ch*4);
        }
        CP_COMMIT();
    };

    stage(0); stage(1); stage(2);

    for(int t=0;t<NT_K;t++){
        cp_wait_tail(NT_K-1-t);
        __syncthreads();
        if(t+3 < NT_K) stage(t+3);
        const float* As = sm + (t&3)*STG;
        const float* Bs = As + ABUF;
#pragma unroll
        for(int kb=0;kb<4;kb++){
            float4 avb[2], avs[2];
#pragma unroll
            for(int mf=0;mf<2;mf++){
                int r = mq*32 + mf*16 + (lane>>2);
                int c = kb*8 + (lane&3);
                float4 av = make_float4(As[r*AST + c],     As[(r+8)*AST + c],
                                        As[r*AST + c + 4], As[(r+8)*AST + c + 4]);
                avb[mf] = make_float4(totf(av.x), totf(av.y), totf(av.z), totf(av.w));
                avs[mf] = make_float4(av.x-avb[mf].x, av.y-avb[mf].y,
                                      av.z-avb[mf].z, av.w-avb[mf].w);
            }
#pragma unroll
            for(int nf=0;nf<4;nf++){
                int bj = (kb*8 + (lane&3))*BST + nq*32 + nf*8 + (lane>>2);
                float2 bv = make_float2(Bs[bj], Bs[bj + 4*BST]);
                float2 bvb = make_float2(totf(bv.x), totf(bv.y));
                float2 bvs = make_float2(bv.x-bvb.x, bv.y-bvb.y);
#pragma unroll
                for(int mf=0;mf<2;mf++){
                    mma8(acc[mf][nf], avb[mf], bvb);
                    mma8(acc[mf][nf], avb[mf], bvs);
                    mma8(acc[mf][nf], avs[mf], bvb);
                }
            }
        }
    }

    const int r0 = i0 + mq*32, c0 = n0 + nq*32;
#pragma unroll
    for(int mf=0;mf<2;mf++){
        int row = r0 + mf*16 + (lane>>2);
        size_t o0 = (size_t)row*256 + c0 + (lane&3)*2;
        size_t o1 = o0 + (size_t)8*256;
#pragma unroll
        for(int nf=0;nf<4;nf++){
            float2 v0 = make_float2(acc[mf][nf][0], acc[mf][nf][1]);
            float2 v1 = make_float2(acc[mf][nf][2], acc[mf][nf][3]);
            *(float2*)(g_Wh + o0 + nf*8) = v0;
            *(float2*)(g_Wh + o1 + nf*8) = v1;
            *(float2*)(g_WhR + o0 + nf*8) = make_float2(totf(v0.x), totf(v0.y));
            *(float2*)(g_WhR + o1 + nf*8) = make_float2(totf(v1.x), totf(v1.y));
        }
    }
}

// ---------------------------------------------------------------------------
// K2: e_src/e_dst projections. One warp per (b,h,n).
// ---------------------------------------------------------------------------
__global__ __launch_bounds__(256)
void gat_attn_proj(const float* __restrict__ a_src, const float* __restrict__ a_dst){
    int r = blockIdx.x*8 + (threadIdx.x>>5);
    int lane = threadIdx.x & 31;
    int b = r>>13, h = (r>>11)&3, n = r & (Nn-1);
    const float* wp = g_Wh + ((size_t)(b*Nn+n))*Dd + h*64;
    float2 w  = *(const float2*)(wp + 2*lane);
    float2 as = *(const float2*)(a_src + h*64 + 2*lane);
    float2 ad = *(const float2*)(a_dst + h*64 + 2*lane);
    float ss = w.x*as.x + w.y*as.y;
    float sd = w.x*ad.x + w.y*ad.y;
#pragma unroll
    for(int o=16;o;o>>=1){
        ss += __shfl_xor_sync(0xffffffffu, ss, o);
        sd += __shfl_xor_sync(0xffffffffu, sd, o);
    }
    if(lane==0){ g_esrc[r]=ss; g_edst[r]=sd; }
}

// ---------------------------------------------------------------------------
// K3: alpha kernel. Block = (b, 8 rows), grid 1024, 256 thr.
// ---------------------------------------------------------------------------
__global__ __launch_bounds__(256)
void gat_alpha(const int* __restrict__ adj, float* __restrict__ alpha_out){
    __shared__ uint8_t bits[8*512];
    __shared__ float es[32], iv[32];
    const int tid = threadIdx.x;
    const int b  = blockIdx.x >> 8;
    const int i0 = (blockIdx.x & 255) * 8;

    if(tid<32) es[tid] = g_esrc[(b*Hh + (tid>>3))*Nn + i0 + (tid&7)];
    __syncthreads();

    {
        const int i = tid>>5, g = tid&31;
        const int*   arow = adj + ((size_t)(b*Nn + i0 + i))*Nn + g*4;
        const float* edb  = g_edst + (size_t)(b*Hh)*Nn + g*4;
        float E[4] = {es[i], es[8+i], es[16+i], es[24+i]};
        float S[4] = {0.f,0.f,0.f,0.f};
#pragma unroll 4
        for(int q=0;q<16;q++){
            int4 a = *(const int4*)(arow + q*128);
            float4 dv[4];
#pragma unroll
            for(int h=0;h<4;h++)
                dv[h] = *(const float4*)(edb + (size_t)h*Nn + q*128);
            int m[4] = {a.x, a.y, a.z, a.w};
#pragma unroll
            for(int jj=0;jj<4;jj++){
                bool mm = m[jj]!=0;
#pragma unroll
                for(int h=0;h<4;h++){
                    float e = E[h] + ((const float*)&dv[h])[jj];
                    e = (e>0.f)?e:0.2f*e;
                    if(mm) S[h] += __expf(e);
                }
            }
            bits[i*512 + q*32 + g] =
                (uint8_t)((m[0]?1u:0u)|(m[1]?2u:0u)|(m[2]?4u:0u)|(m[3]?8u:0u));
        }
#pragma unroll
        for(int h=0;h<4;h++)
#pragma unroll
            for(int o=16;o;o>>=1)
                S[h] += __shfl_xor_sync(0xffffffffu, S[h], o);
        if(g==0)
#pragma unroll
            for(int h=0;h<4;h++)
                iv[h*8+i] = (S[h]>0.f) ? (1.f/S[h]) : 0.f;
    }
    __syncthreads();

    const int h = tid>>6, c = tid&63;
    const float* edp = g_edst + (size_t)(b*Hh+h)*Nn;
    float* ab = alpha_out + ((size_t)((b*Hh+h)*Nn) + i0)*Nn;
    const float* esh = es + h*8;
    const float* ivh = iv + h*8;
#pragma unroll
    for(int jc=0;jc<8;jc++){
        const int j = jc*256 + c*4;
        float4 ed = *(const float4*)(edp + j);
#pragma unroll
        for(int i=0;i<8;i++){
            float E = esh[i], V = ivh[i];
            uint32_t nib = bits[i*512 + (j>>2)];
            float4 o; float e;
            e=E+ed.x; e=(e>0.f)?e:0.2f*e; o.x = (nib&1u)?__expf(e)*V:0.f;
            e=E+ed.y; e=(e>0.f)?e:0.2f*e; o.y = (nib&2u)?__expf(e)*V:0.f;
            e=E+ed.z; e=(e>0.f)?e:0.2f*e; o.z = (nib&4u)?__expf(e)*V:0.f;
            e=E+ed.w; e=(e>0.f)?e:0.2f*e; o.w = (nib&8u)?__expf(e)*V:0.f;
            *(float4*)(ab + (size_t)i*Nn + j) = o;
        }
    }
}

// ---------------------------------------------------------------------------
// K4: split-K GEMM. grid (32,16): x = i-tile(0..15) | ks<<4. Each block does
// K=1024 (32 tiles), 2-stage pipeline, 3 CTA/SM. Partials to g_p0/g_p1.
// ---------------------------------------------------------------------------
__global__ __launch_bounds__(256,3)
void gat_gemm(const float* __restrict__ alpha){
    extern __shared__ float sm[];
    const int tid = threadIdx.x, lane = tid & 31;
    const int bh = blockIdx.y, b = bh>>2, h = bh&3;
    const int it = blockIdx.x & 15, ks = blockIdx.x >> 4;
    const int i0 = it * 128;
    const int NT2 = 32;
    const float* abase = alpha + ((size_t)bh*Nn + i0)*Nn + ks*1024;
    const float* wbase = g_WhR + (size_t)b*Nn*Dd + (size_t)ks*1024*Dd + h*64;
    float* pout = ks ? g_p1 : g_p0;

    const int mq = (tid>>5)&3, nq = tid>>7;

    float acc[2][4][4];
#pragma unroll
    for(int mf=0;mf<2;mf++)
#pragma unroll
        for(int nf=0;nf<4;nf++)
#pragma unroll
            for(int q=0;q<4;q++) acc[mf][nf][q]=0.f;

    const int a_row = tid>>3, a_ch = tid&7;
    const int b_j   = tid>>4, b_ch = tid&15;

    auto stage = [&](int t){
        const int j0 = t*TJ;
        float* Asm = sm + (t&1)*STG;
        float* Bsm = Asm + ABUF;
#pragma unroll
        for(int k=0;k<4;k++){
            int row = a_row + k*32;
            cpasync16(Asm + row*AST + a_ch*4,
                      abase + (size_t)row*Nn + j0 + a_ch*4);
        }
#pragma unroll
        for(int k=0;k<2;k++){
            int j = b_j + k*16;
            cpasync16(Bsm + j*BST + b_ch*4,
                      wbase + (size_t)(j0+j)*Dd + b_ch*4);
        }
        CP_COMMIT();
    };

    stage(0); stage(1);

    for(int t=0;t<NT2;t++){
        cp_wait_tail(t+1<NT2 ? 1 : 0);
        __syncthreads();
        const float* As = sm + (t&1)*STG;
        const float* Bs = As + ABUF;
#pragma unroll
        for(int kb=0;kb<4;kb++){
            float4 av[2];
#pragma unroll
            for(int mf=0;mf<2;mf++){
                int r = mq*32 + mf*16 + (lane>>2);
                int c = kb*8 + (lane&3);
                av[mf] = make_float4(As[r*AST + c],     As[(r+8)*AST + c],
                                     As[r*AST + c + 4], As[(r+8)*AST + c + 4]);
            }
            float2 bv[4];
#pragma unroll
            for(int nf=0;nf<4;nf++){
                int bj = (kb*8 + (lane&3))*BST + nq*32 + nf*8 + (lane>>2);
                bv[nf] = make_float2(Bs[bj], Bs[bj + 4*BST]);
            }
#pragma unroll
            for(int mf=0;mf<2;mf++)
#pragma unroll
                for(int nf=0;nf<4;nf++)
                    mma8(acc[mf][nf], av[mf], bv[nf]);
        }
        __syncthreads();
        if(t+2 < NT2) stage(t+2);
    }

    const int r0 = i0 + mq*32, c0 = h*64 + nq*32;
#pragma unroll
    for(int mf=0;mf<2;mf++){
        int row = r0 + mf*16 + (lane>>2);
        float* p0 = pout + ((size_t)(b*Nn) + row)*Dd + c0 + (lane&3)*2;
        float* p1 = p0 + (size_t)8*Dd;
#pragma unroll
        for(int nf=0;nf<4;nf++){
            *(float2*)(p0 + nf*8) = make_float2(acc[mf][nf][0], acc[mf][nf][1]);
            *(float2*)(p1 + nf*8) = make_float2(acc[mf][nf][2], acc[mf][nf][3]);
        }
    }
}

// ---------------------------------------------------------------------------
// K5: out = p0 + p1
// ---------------------------------------------------------------------------
__global__ __launch_bounds__(256)
void gat_reduce(float* __restrict__ out){
    size_t i = ((size_t)blockIdx.x*256 + threadIdx.x)*4;
    float4 a=*(const float4*)(g_p0+i);
    float4 b=*(const float4*)(g_p1+i);
    a.x+=b.x; a.y+=b.y; a.z+=b.z; a.w+=b.w;
    *(float4*)(out+i)=a;
}

// ---------------------------------------------------------------------------
extern "C" void kernel_launch(void* const* d_in, const int* in_sizes, int n_in,
                              void* d_out, int out_size){
    const float* h     = (const float*)d_in[0];
    const int*   adj   = (const int*)d_in[1];
    const float* W     = (const float*)d_in[2];
    const float* a_src = (const float*)d_in[3];
    const float* a_dst = (const float*)d_in[4];
    float* out = (float*)d_out;

    const long long houtN  = (long long)Bc*Nn*Dd;
    const long long alphaN = (long long)Bc*Hh*Nn*Nn;
    bool has_alpha = ((long long)out_size >= houtN + alphaN);
    float* alpha_buf;
    if(has_alpha){
        alpha_buf = out + houtN;
    } else {
        cudaGetSymbolAddress((void**)&alpha_buf, g_alpha_s);
    }

    cudaFuncSetAttribute(gemm_h_w, cudaFuncAttributeMaxDynamicSharedMemorySize,
                         SMEM_PIPE4);
    cudaFuncSetAttribute(gat_gemm, cudaFuncAttributeMaxDynamicSharedMemorySize,
                         SMEM_PIPE2);

    gemm_h_w<<<dim3(64,4),256,SMEM_PIPE4>>>(h, W);
    gat_attn_proj<<<(Bc*Hh*Nn)/8,256>>>(a_src, a_dst);
    gat_alpha<<<Bc*256,256>>>(adj, alpha_buf);
    gat_gemm<<<dim3(32,16),256,SMEM_PIPE2>>>(alpha_buf);
    gat_reduce<<<(Bc*Nn*Dd)/(256*4),256>>>(out);
}